// round 16
// baseline (speedup 1.0000x reference)
#include <cuda_runtime.h>
#include <cuda_fp16.h>
#include <cstdint>
#include <math.h>

// ---------------- problem constants ----------------
#define BATCH   4
#define CDIM    128
#define HH      128
#define WW      128
#define RS      16
#define STEP    14
#define NR      9
#define NREG    (BATCH*NR*NR)      // 324
#define NTOK    (RS*RS)            // 256
#define TOTTOK  (NREG*NTOK)        // 82944
#define NHEADS  4
#define HD      32
#define HIDDEN  256
#define NPIX    (HH*WW)            // 16384
#define TOTPIX  (BATCH*NPIX)       // 65536

// ---------------- scratch ----------------
__device__ __half g_tok_raw_h[(size_t)TOTTOK*CDIM];
__device__ __half g_yln_h [(size_t)TOTTOK*CDIM];
__device__ __half g_qkv_h [(size_t)TOTTOK*3*CDIM];
__device__ __half g_oattn_h[(size_t)TOTTOK*CDIM];
__device__ __half g_tok2_h[(size_t)TOTTOK*CDIM];
__device__ __half g_xf_h  [(size_t)TOTPIX*CDIM];
__device__ __half g_y2_h  [(size_t)TOTPIX*CDIM];
__device__ __half g_h0_h  [(size_t)TOTPIX*HIDDEN];
__device__ __half g_conv_h[(size_t)TOTPIX*HIDDEN];
__device__ float  g_part  [2*512*HIDDEN];
__device__ float  g_mid   [2*32*HIDDEN];
__device__ float  g_bnp   [2*HIDDEN];
// fp16 transposed weights [N][K]
__device__ __half g_wqkv_h[384*128];
__device__ __half g_wout_h[128*128];
__device__ __half g_wp0_h [256*128];
__device__ __half g_wp2_h [128*256];

// ---------------- helpers ----------------
__device__ __forceinline__ float gelu_exact(float x) {
    return 0.5f * x * (1.0f + erff(x * 0.70710678118654752f));
}
__device__ __forceinline__ unsigned pack_h2(float a, float b) {
    __half2 h = __floats2half2_rn(a, b);
    return *(unsigned*)&h;
}
__device__ __forceinline__ float ex2(float x) {
    float y; asm("ex2.approx.ftz.f32 %0, %1;" : "=f"(y) : "f"(x)); return y;
}
__device__ __forceinline__ void mma_f16(float* c, const unsigned* a, const unsigned* b) {
    asm volatile(
        "mma.sync.aligned.m16n8k16.row.col.f32.f16.f16.f32 "
        "{%0,%1,%2,%3},{%4,%5,%6,%7},{%8,%9},{%0,%1,%2,%3};"
        : "+f"(c[0]), "+f"(c[1]), "+f"(c[2]), "+f"(c[3])
        : "r"(a[0]), "r"(a[1]), "r"(a[2]), "r"(a[3]), "r"(b[0]), "r"(b[1]));
}
__device__ __forceinline__ void ldsm4(unsigned& r0, unsigned& r1, unsigned& r2, unsigned& r3,
                                      unsigned addr) {
    asm volatile("ldmatrix.sync.aligned.m8n8.x4.shared.b16 {%0,%1,%2,%3}, [%4];"
                 : "=r"(r0), "=r"(r1), "=r"(r2), "=r"(r3) : "r"(addr));
}
__device__ __forceinline__ void ldsm4t(unsigned& r0, unsigned& r1, unsigned& r2, unsigned& r3,
                                       unsigned addr) {
    asm volatile("ldmatrix.sync.aligned.m8n8.x4.trans.shared.b16 {%0,%1,%2,%3}, [%4];"
                 : "=r"(r0), "=r"(r1), "=r"(r2), "=r"(r3) : "r"(addr));
}
__device__ __forceinline__ void cp16(void* smem_dst, const void* gsrc) {
    unsigned d = (unsigned)__cvta_generic_to_shared(smem_dst);
    asm volatile("cp.async.cg.shared.global [%0], [%1], 16;\n" :: "r"(d), "l"(gsrc));
}

// ---------------- kernel 1: merged weight-convert + region gather + LN1 ----------------
__device__ void wconv_body(int blk, int tid,
                           const float* wqkv, const float* wout,
                           const float* wp0, const float* wp2) {
    int idx = blk * 256 + tid;
    const float* in; __half* out; int K, local;
    int N;
    if (idx < 49152)       { in = wqkv; out = g_wqkv_h; K = 128; N = 384; local = idx; }
    else if (idx < 65536)  { in = wout; out = g_wout_h; K = 128; N = 128; local = idx - 49152; }
    else if (idx < 98304)  { in = wp0;  out = g_wp0_h;  K = 128; N = 256; local = idx - 65536; }
    else                   { in = wp2;  out = g_wp2_h;  K = 256; N = 128; local = idx - 98304; }
    int n = local / K, k = local % K;
    out[local] = __float2half(in[k * N + n]);
}

__global__ void k_front(const float* __restrict__ x,
                        const float* __restrict__ g,
                        const float* __restrict__ b,
                        const float* __restrict__ wqkv, const float* __restrict__ wout,
                        const float* __restrict__ wp0,  const float* __restrict__ wp2) {
    __shared__ float sTok[8][132];
    int tid = threadIdx.x;
    if (blockIdx.x < 512) { wconv_body(blockIdx.x, tid, wqkv, wout, wp0, wp2); return; }
    int blk = blockIdx.x - 512;
    int grp = blk & 1;
    int ti  = (blk >> 1) & 15;
    int region = blk >> 5;
    int breg = region / (NR * NR);
    int rem  = region % (NR * NR);
    int rr = rem / NR, rc = rem % NR;
    int hh = rr * STEP + ti;
    int ww0 = rc * STEP + grp * 8;
    int tj8 = tid & 7;
    int cbase = tid >> 3;
    #pragma unroll
    for (int chunk = 0; chunk < 4; chunk++) {
        int c = cbase + chunk * 32;
        sTok[tj8][c] = x[(((size_t)breg * CDIM + c) * HH + hh) * WW + ww0 + tj8];
    }
    __syncthreads();
    int w = tid >> 5, lane = tid & 31;
    float4 v = *(const float4*)&sTok[w][lane * 4];
    float sum = v.x + v.y + v.z + v.w;
    float sq  = v.x*v.x + v.y*v.y + v.z*v.z + v.w*v.w;
    #pragma unroll
    for (int o = 16; o > 0; o >>= 1) {
        sum += __shfl_xor_sync(0xffffffffu, sum, o);
        sq  += __shfl_xor_sync(0xffffffffu, sq,  o);
    }
    float mean = sum * (1.0f / 128.0f);
    float invstd = rsqrtf(sq * (1.0f / 128.0f) - mean * mean + 1e-5f);
    int tok = region * NTOK + ti * 16 + grp * 8 + w;
    float4 gg = *(const float4*)(g + lane * 4);
    float4 bb = *(const float4*)(b + lane * 4);
    size_t o = (size_t)tok * CDIM + lane * 4;
    __half2* tp = (__half2*)(g_tok_raw_h + o);
    tp[0] = __floats2half2_rn(v.x, v.y);
    tp[1] = __floats2half2_rn(v.z, v.w);
    float y0 = (v.x - mean) * invstd * gg.x + bb.x;
    float y1 = (v.y - mean) * invstd * gg.y + bb.y;
    float y2 = (v.z - mean) * invstd * gg.z + bb.z;
    float y3 = (v.w - mean) * invstd * gg.w + bb.w;
    __half2* yp = (__half2*)(g_yln_h + o);
    yp[0] = __floats2half2_rn(y0, y1);
    yp[1] = __floats2half2_rn(y2, y3);
}

// ---------------- pipelined fp16 tensor-core GEMM, BK=32 ----------------
#define ASTRIDE 40
#define ABUF    (64*ASTRIDE)
#define BSTRIDE 40
#define BBUF    (128*BSTRIDE)
#define ST_STRIDE 72

__global__ void __launch_bounds__(256) gemm_f16(
        const __half* __restrict__ Ah, const __half* __restrict__ B,
        const float* __restrict__ bias, const __half* __restrict__ resh,
        void* __restrict__ Cp, int M, int N, int K, int mode,
        const float* __restrict__ actp) {
    __shared__ __align__(16) char smem_raw[36864];
    __half* As = (__half*)smem_raw;                  // [2][64][40]
    __half* Bs = (__half*)(smem_raw + 2 * ABUF * 2); // [2][128][40]
    int bm = blockIdx.y * 64, bn = blockIdx.x * 128;
    int tid = threadIdx.x, lane = tid & 31, wid = tid >> 5;
    int wm = wid & 1, wn = wid >> 1;
    int lr = lane >> 2, lc = lane & 3;

    float* Cf = (float*)Cp;
    __half* Ch = (__half*)Cp;

    float acc[2][4][4];
    #pragma unroll
    for (int i = 0; i < 2; i++)
        #pragma unroll
        for (int j = 0; j < 4; j++)
            #pragma unroll
            for (int t = 0; t < 4; t++) acc[i][j][t] = 0.f;

    float a8v[8];
    int arow = tid >> 2, ac = tid & 3;
    auto prefetchA = [&](int k0, int buf) {
        cp16(As + buf * ABUF + arow * ASTRIDE + ac * 8,
             Ah + (size_t)(bm + arow) * K + k0 + ac * 8);
    };
    auto prefetchB = [&](int k0, int buf) {
        #pragma unroll
        for (int i = 0; i < 2; i++) {
            int id = tid * 2 + i;
            int brow = id >> 2, bc = id & 3;
            cp16(Bs + buf * BBUF + brow * BSTRIDE + bc * 8,
                 B + (size_t)(bn + brow) * K + k0 + bc * 8);
        }
    };
    auto ldgA = [&](int k0) {
        uint4 u = *(const uint4*)(Ah + (size_t)(bm + arow) * K + k0 + ac * 8);
        float2 f0 = __half22float2(*(__half2*)&u.x);
        float2 f1 = __half22float2(*(__half2*)&u.y);
        float2 f2 = __half22float2(*(__half2*)&u.z);
        float2 f3 = __half22float2(*(__half2*)&u.w);
        a8v[0] = f0.x; a8v[1] = f0.y; a8v[2] = f1.x; a8v[3] = f1.y;
        a8v[4] = f2.x; a8v[5] = f2.y; a8v[6] = f3.x; a8v[7] = f3.y;
    };
    auto actStsA = [&](int k0, int buf) {
        int ch = k0 + ac * 8;
        __half2* dp = (__half2*)(As + buf * ABUF + arow * ASTRIDE + ac * 8);
        #pragma unroll
        for (int u = 0; u < 4; u++) {
            float v0 = gelu_exact(gelu_exact(a8v[2*u]   * actp[ch+2*u]   + actp[HIDDEN+ch+2*u]));
            float v1 = gelu_exact(gelu_exact(a8v[2*u+1] * actp[ch+2*u+1] + actp[HIDDEN+ch+2*u+1]));
            dp[u] = __floats2half2_rn(v0, v1);
        }
    };

    int rowoff = ((lane >> 3) & 1) * 8 + (lane & 7);
    int coloff = (lane >> 4) * 8;
    unsigned abase = (unsigned)__cvta_generic_to_shared(
        As + (wm * 32 + rowoff) * ASTRIDE + coloff);
    unsigned bbase = (unsigned)__cvta_generic_to_shared(
        Bs + (wn * 32 + rowoff) * BSTRIDE + coloff);
    const unsigned ABUFB = ABUF * 2, BBUFB = BBUF * 2;
    const unsigned AI16  = 16 * ASTRIDE * 2;
    const unsigned BN16  = 16 * BSTRIDE * 2;

    int T = K >> 5;
    if (actp) { ldgA(0); actStsA(0, 0); prefetchB(0, 0); }
    else      { prefetchA(0, 0); prefetchB(0, 0); }
    asm volatile("cp.async.commit_group;\n");

    for (int t = 0; t < T; t++) {
        int buf = t & 1;
        asm volatile("cp.async.wait_group 0;\n");
        __syncthreads();
        if (t + 1 < T) {
            int k1 = (t + 1) << 5;
            if (actp) { ldgA(k1); prefetchB(k1, buf ^ 1); }
            else      { prefetchA(k1, buf ^ 1); prefetchB(k1, buf ^ 1); }
            asm volatile("cp.async.commit_group;\n");
        }
        #pragma unroll
        for (int ks = 0; ks < 2; ks++) {
            unsigned a[2][4], bf[4][2];
            ldsm4(a[0][0], a[0][1], a[0][2], a[0][3],
                  abase + buf * ABUFB + ks * 32);
            ldsm4(a[1][0], a[1][1], a[1][2], a[1][3],
                  abase + buf * ABUFB + AI16 + ks * 32);
            ldsm4(bf[0][0], bf[1][0], bf[0][1], bf[1][1],
                  bbase + buf * BBUFB + ks * 32);
            ldsm4(bf[2][0], bf[3][0], bf[2][1], bf[3][1],
                  bbase + buf * BBUFB + BN16 + ks * 32);
            #pragma unroll
            for (int i = 0; i < 2; i++)
                #pragma unroll
                for (int j = 0; j < 4; j++)
                    mma_f16(acc[i][j], a[i], bf[j]);
        }
        if (actp && t + 1 < T) actStsA((t + 1) << 5, buf ^ 1);
    }

    if (mode == 2 || mode == 3) {
        #pragma unroll
        for (int i = 0; i < 2; i++) {
            int r0 = bm + wm * 32 + i * 16 + lr;
            #pragma unroll
            for (int j = 0; j < 4; j++) {
                int c0 = bn + wn * 32 + j * 8 + lc * 2;
                float b0 = bias ? bias[c0] : 0.f, b1 = bias ? bias[c0 + 1] : 0.f;
                float v00 = acc[i][j][0] + b0, v01 = acc[i][j][1] + b1;
                float v10 = acc[i][j][2] + b0, v11 = acc[i][j][3] + b1;
                if (mode == 3) {
                    float2 r0f = __half22float2(*(const __half2*)(resh + (size_t)r0 * N + c0));
                    float2 r1f = __half22float2(*(const __half2*)(resh + (size_t)(r0 + 8) * N + c0));
                    v00 += r0f.x; v01 += r0f.y; v10 += r1f.x; v11 += r1f.y;
                }
                *(__half2*)(Ch + (size_t)r0 * N + c0) = __floats2half2_rn(v00, v01);
                *(__half2*)(Ch + (size_t)(r0 + 8) * N + c0) = __floats2half2_rn(v10, v11);
            }
        }
    } else {
        float* sT = (float*)smem_raw;    // [128][72]
        __syncthreads();
        #pragma unroll
        for (int i = 0; i < 2; i++)
            #pragma unroll
            for (int j = 0; j < 4; j++)
                #pragma unroll
                for (int t = 0; t < 4; t++) {
                    int m = wm * 32 + i * 16 + (t >> 1) * 8 + lr;
                    int nr = wn * 32 + j * 8 + lc * 2 + (t & 1);
                    int n = bn + nr;
                    float v = acc[i][j][t];
                    if (bias) v += bias[n];
                    if (resh) v += __half2float(resh[(size_t)(bm + m) * N + n]);
                    sT[nr * ST_STRIDE + m] = v;
                }
        __syncthreads();
        int bidx = bm >> 14, p0 = bm & 16383;
        int nrow = tid >> 1, seg = tid & 1;
        const float* srcrow = sT + nrow * ST_STRIDE;
        float* dst = Cf + ((size_t)(bidx * 128 + bn + nrow)) * 16384 + p0;
        #pragma unroll
        for (int u = 0; u < 8; u++) {
            int f = seg * 32 + u * 4;
            float4 v = *(const float4*)(srcrow + f);
            *(float4*)(dst + f) = v;
        }
    }
}

// ---------------- kernel 3: fp16 flash attention, 64-key chunks ----------------
#define KVSTRIDE 40   // halves per row
__global__ void __launch_bounds__(256, 3) k_attn_mma() {
    __shared__ __half Ks[2][64][KVSTRIDE];
    __shared__ __half Vs[2][64][KVSTRIDE];
    int region = blockIdx.x >> 2;
    int head   = blockIdx.x & 3;
    const __half* base = g_qkv_h + (size_t)region * NTOK * 384;
    int hoff = head * HD;
    int tid = threadIdx.x, lane = tid & 31, w = tid >> 5;
    int lr = lane >> 2, lc = lane & 3;
    const float qscale = 0.17677669529663687f * 1.44269504088896341f;

    unsigned aq[2][2][4];
    #pragma unroll
    for (int kstep = 0; kstep < 2; kstep++)
        #pragma unroll
        for (int i = 0; i < 2; i++) {
            int r = w * 32 + i * 16 + lr;
            const __half* qp = base + (size_t)r * 384 + hoff + kstep * 16;
            unsigned u[4];
            u[0] = *(const unsigned*)(qp + 2 * lc);
            u[1] = *(const unsigned*)(qp + 8 * 384 + 2 * lc);
            u[2] = *(const unsigned*)(qp + 2 * lc + 8);
            u[3] = *(const unsigned*)(qp + 8 * 384 + 2 * lc + 8);
            #pragma unroll
            for (int t = 0; t < 4; t++) {
                float2 f = __half22float2(*(__half2*)&u[t]);
                aq[kstep][i][t] = pack_h2(f.x * qscale, f.y * qscale);
            }
        }

    float l[2][2], o[2][4][4];
    #pragma unroll
    for (int i = 0; i < 2; i++)
        #pragma unroll
        for (int h = 0; h < 2; h++) l[i][h] = 0.f;
    #pragma unroll
    for (int i = 0; i < 2; i++)
        #pragma unroll
        for (int jo = 0; jo < 4; jo++)
            #pragma unroll
            for (int t = 0; t < 4; t++) o[i][jo][t] = 0.f;

    int tile = lane >> 3, trow = lane & 7;
    unsigned kaddr = (unsigned)__cvta_generic_to_shared(
        &Ks[0][(tile >> 1) * 8 + trow][(tile & 1) * 8]);
    unsigned vaddr = (unsigned)__cvta_generic_to_shared(
        &Vs[0][(tile & 1) * 8 + trow][(tile >> 1) * 8]);
    const unsigned BUFOFF  = 64 * KVSTRIDE * 2;
    const unsigned HALFOFF = 32 * KVSTRIDE * 2;
    const unsigned J2OFF   = 16 * KVSTRIDE * 2;
    const unsigned KS_K    = 32;
    const unsigned KS_V    = 16 * KVSTRIDE * 2;
    const unsigned JO2_V   = 32;

    int lrw = tid >> 2, lch = tid & 3;    // 64 rows x 4 16B-chunks
    auto loadKV = [&](int c0, int buf) {
        const __half* rp = base + (size_t)(c0 + lrw) * 384 + 128 + hoff + lch * 8;
        cp16(&Ks[buf][lrw][lch * 8], rp);
        cp16(&Vs[buf][lrw][lch * 8], rp + 128);
        asm volatile("cp.async.commit_group;\n");
    };

    loadKV(0, 0);
    for (int t = 0; t < 4; t++) {
        int buf = t & 1;
        asm volatile("cp.async.wait_group 0;\n");
        __syncthreads();
        if (t < 3) loadKV((t + 1) * 64, buf ^ 1);

        #pragma unroll
        for (int half = 0; half < 2; half++) {
            unsigned kb = kaddr + buf * BUFOFF + half * HALFOFF;
            unsigned vb = vaddr + buf * BUFOFF + half * HALFOFF;

            float s[2][4][4];
            #pragma unroll
            for (int i = 0; i < 2; i++)
                #pragma unroll
                for (int j = 0; j < 4; j++)
                    #pragma unroll
                    for (int tt = 0; tt < 4; tt++) s[i][j][tt] = 0.f;
            #pragma unroll
            for (int kstep = 0; kstep < 2; kstep++) {
                unsigned bf[4][2];
                ldsm4(bf[0][0], bf[0][1], bf[1][0], bf[1][1], kb + kstep * KS_K);
                ldsm4(bf[2][0], bf[2][1], bf[3][0], bf[3][1], kb + kstep * KS_K + J2OFF);
                #pragma unroll
                for (int i = 0; i < 2; i++)
                    #pragma unroll
                    for (int j = 0; j < 4; j++)
                        mma_f16(s[i][j], aq[kstep][i], bf[j]);
            }

            #pragma unroll
            for (int i = 0; i < 2; i++) {
                #pragma unroll
                for (int j = 0; j < 4; j++) {
                    s[i][j][0] = ex2(s[i][j][0]);
                    s[i][j][1] = ex2(s[i][j][1]);
                    s[i][j][2] = ex2(s[i][j][2]);
                    s[i][j][3] = ex2(s[i][j][3]);
                    l[i][0] += s[i][j][0] + s[i][j][1];
                    l[i][1] += s[i][j][2] + s[i][j][3];
                }
            }

            #pragma unroll
            for (int kstep = 0; kstep < 2; kstep++) {
                unsigned bv[4][2];
                ldsm4t(bv[0][0], bv[0][1], bv[1][0], bv[1][1], vb + kstep * KS_V);
                ldsm4t(bv[2][0], bv[2][1], bv[3][0], bv[3][1], vb + kstep * KS_V + JO2_V);
                #pragma unroll
                for (int i = 0; i < 2; i++) {
                    unsigned ap[4];
                    ap[0] = pack_h2(s[i][2 * kstep][0],     s[i][2 * kstep][1]);
                    ap[1] = pack_h2(s[i][2 * kstep][2],     s[i][2 * kstep][3]);
                    ap[2] = pack_h2(s[i][2 * kstep + 1][0], s[i][2 * kstep + 1][1]);
                    ap[3] = pack_h2(s[i][2 * kstep + 1][2], s[i][2 * kstep + 1][3]);
                    #pragma unroll
                    for (int jo = 0; jo < 4; jo++)
                        mma_f16(o[i][jo], ap, bv[jo]);
                }
            }
        }
    }

    #pragma unroll
    for (int i = 0; i < 2; i++)
        #pragma unroll
        for (int h = 0; h < 2; h++)
            #pragma unroll
            for (int off = 1; off <= 2; off <<= 1)
                l[i][h] += __shfl_xor_sync(0xffffffffu, l[i][h], off);

    #pragma unroll
    for (int i = 0; i < 2; i++) {
        float inv0 = 1.0f / l[i][0], inv1 = 1.0f / l[i][1];
        #pragma unroll
        for (int h = 0; h < 2; h++) {
            int q = w * 32 + i * 16 + lr + h * 8;
            float inv = h ? inv1 : inv0;
            __half* op = g_oattn_h + ((size_t)region * NTOK + q) * CDIM + hoff;
            #pragma unroll
            for (int jo = 0; jo < 4; jo++) {
                *(__half2*)(op + jo * 8 + lc * 2) =
                    __floats2half2_rn(o[i][jo][h * 2 + 0] * inv,
                                      o[i][jo][h * 2 + 1] * inv);
            }
        }
    }
}

// ---------------- kernel 5: overlap-merge + LN2, 2 pixels/block ----------------
__global__ void k_merge_ln2(const float* __restrict__ g, const float* __restrict__ b) {
    __shared__ float s1[8], s2[8];
    int tid = threadIdx.x;
    int pix = blockIdx.x * 2 + (tid >> 7);
    int c = tid & 127;
    int bidx = pix >> 14;
    int p = pix & 16383;
    int hh = p >> 7, ww = p & 127;
    int rlo = max(0, (hh - 2) / STEP), rhi = min(NR - 1, hh / STEP);
    int clo = max(0, (ww - 2) / STEP), chi = min(NR - 1, ww / STEP);
    float sum = 0.f;
    int cnt = (rhi - rlo + 1) * (chi - clo + 1);
    for (int rr = rlo; rr <= rhi; rr++)
        for (int rc = clo; rc <= chi; rc++) {
            int region = bidx * (NR * NR) + rr * NR + rc;
            int t = (hh - rr * STEP) * RS + (ww - rc * STEP);
            sum += __half2float(g_tok2_h[((size_t)region * NTOK + t) * CDIM + c]);
        }
    float v = sum / (float)cnt;
    float su = v, sq = v * v;
    #pragma unroll
    for (int o = 16; o > 0; o >>= 1) {
        su += __shfl_xor_sync(0xffffffffu, su, o);
        sq += __shfl_xor_sync(0xffffffffu, sq, o);
    }
    int w = tid >> 5;
    if ((tid & 31) == 0) { s1[w] = su; s2[w] = sq; }
    __syncthreads();
    int base4 = (tid >> 7) * 4;
    float ts = s1[base4] + s1[base4+1] + s1[base4+2] + s1[base4+3];
    float tq = s2[base4] + s2[base4+1] + s2[base4+2] + s2[base4+3];
    float mean = ts * (1.0f / 128.0f);
    float invstd = rsqrtf(tq * (1.0f / 128.0f) - mean * mean + 1e-5f);
    size_t o = (size_t)pix * CDIM + c;
    g_xf_h[o] = __float2half(v);
    g_y2_h[o] = __float2half((v - mean) * invstd * g[c] + b[c]);
}

// ---------------- kernel 7: row-blocked depthwise 5x5 conv (fp16) + BN partials ----------------
__global__ void k_dwconv(const float* __restrict__ k5) {
    int blk = blockIdx.x;                // 512
    int cg = blk & 3;
    int rg = (blk >> 2) & 31;
    int bidx = blk >> 7;
    int ch = threadIdx.x;
    int hh0 = rg * 4;
    int w0 = cg * 32;
    float kw[25];
    #pragma unroll
    for (int i = 0; i < 25; i++) kw[i] = k5[ch * 25 + i];
    const __half* base = g_h0_h + (size_t)bidx * NPIX * HIDDEN + ch;
    float win[5][8];
    auto loadcol = [&](int xx, float* col) {
        #pragma unroll
        for (int ry = 0; ry < 8; ry++) {
            int yy = hh0 - 2 + ry;
            col[ry] = ((unsigned)xx < (unsigned)WW && (unsigned)yy < (unsigned)HH)
                      ? __half2float(base[((size_t)(yy * WW + xx)) * HIDDEN]) : 0.f;
        }
    };
    #pragma unroll
    for (int xi = 0; xi < 4; xi++) loadcol(w0 - 2 + xi, win[xi]);
    float psum = 0.f, psq = 0.f;
    __half* outb = g_conv_h + ((size_t)bidx * NPIX + hh0 * WW) * HIDDEN + ch;
    for (int ww = w0; ww < w0 + 32; ww++) {
        loadcol(ww + 2, win[4]);
        #pragma unroll
        for (int r = 0; r < 4; r++) {
            float acc = 0.f;
            #pragma unroll
            for (int dy = 0; dy < 5; dy++)
                #pragma unroll
                for (int dx = 0; dx < 5; dx++)
                    acc += win[dx][r + dy] * kw[dy * 5 + dx];
            outb[((size_t)(r * WW + ww)) * HIDDEN] = __float2half(acc);
            psum += acc; psq += acc * acc;
        }
        #pragma unroll
        for (int xi = 0; xi < 4; xi++)
            #pragma unroll
            for (int ry = 0; ry < 8; ry++) win[xi][ry] = win[xi + 1][ry];
    }
    g_part[blk * HIDDEN + ch] = psum;
    g_part[512 * HIDDEN + blk * HIDDEN + ch] = psq;
}

// ---------------- batchnorm reduction ----------------
__global__ void k_bnmid() {
    int ch = threadIdx.x;
    int b = blockIdx.x;
    float s = 0.f, q = 0.f;
    for (int i = 0; i < 16; i++) {
        int idx = (b * 16 + i) * HIDDEN + ch;
        s += g_part[idx];
        q += g_part[512 * HIDDEN + idx];
    }
    g_mid[b * HIDDEN + ch] = s;
    g_mid[32 * HIDDEN + b * HIDDEN + ch] = q;
}
__global__ void k_bnfinal(const float* __restrict__ bg, const float* __restrict__ bb) {
    int ch = threadIdx.x;
    float s = 0.f, q = 0.f;
    for (int i = 0; i < 32; i++) {
        s += g_mid[i * HIDDEN + ch];
        q += g_mid[32 * HIDDEN + i * HIDDEN + ch];
    }
    float mean = s * (1.0f / (float)TOTPIX);
    float var  = q * (1.0f / (float)TOTPIX) - mean * mean;
    float sc = bg[ch] * rsqrtf(var + 1e-5f);
    g_bnp[ch] = sc;
    g_bnp[HIDDEN + ch] = bb[ch] - mean * sc;
}

// ---------------- host launcher ----------------
extern "C" void kernel_launch(void* const* d_in, const int* in_sizes, int n_in,
                              void* d_out, int out_size) {
    const float* x      = (const float*)d_in[0];
    const float* ln1_g  = (const float*)d_in[1];
    const float* ln1_b  = (const float*)d_in[2];
    const float* w_qkv  = (const float*)d_in[3];
    const float* w_out  = (const float*)d_in[4];
    const float* b_out  = (const float*)d_in[5];
    const float* ln2_g  = (const float*)d_in[6];
    const float* ln2_b  = (const float*)d_in[7];
    const float* w_p0   = (const float*)d_in[8];
    const float* b_p0   = (const float*)d_in[9];
    const float* dw_k   = (const float*)d_in[10];
    const float* bn_g   = (const float*)d_in[11];
    const float* bn_b   = (const float*)d_in[12];
    const float* w_p2   = (const float*)d_in[13];
    const float* b_p2   = (const float*)d_in[14];
    (void)in_sizes; (void)n_in; (void)out_size;

    float *bnp;
    __half *tok_raw_h, *yln_h, *qkv_h, *oattn_h, *tok2_h, *xf_h, *y2_h, *h0_h, *conv_h;
    __half *wqkv_h, *wout_h, *wp0_h, *wp2_h;
    cudaGetSymbolAddress((void**)&tok_raw_h, g_tok_raw_h);
    cudaGetSymbolAddress((void**)&yln_h,   g_yln_h);
    cudaGetSymbolAddress((void**)&qkv_h,   g_qkv_h);
    cudaGetSymbolAddress((void**)&oattn_h, g_oattn_h);
    cudaGetSymbolAddress((void**)&tok2_h,  g_tok2_h);
    cudaGetSymbolAddress((void**)&xf_h,    g_xf_h);
    cudaGetSymbolAddress((void**)&y2_h,    g_y2_h);
    cudaGetSymbolAddress((void**)&h0_h,    g_h0_h);
    cudaGetSymbolAddress((void**)&conv_h,  g_conv_h);
    cudaGetSymbolAddress((void**)&bnp,     g_bnp);
    cudaGetSymbolAddress((void**)&wqkv_h,  g_wqkv_h);
    cudaGetSymbolAddress((void**)&wout_h,  g_wout_h);
    cudaGetSymbolAddress((void**)&wp0_h,   g_wp0_h);
    cudaGetSymbolAddress((void**)&wp2_h,   g_wp2_h);

    // 1. merged: weight convert + region gather + LN1
    k_front<<<512 + TOTTOK / 8, 256>>>(x, ln1_g, ln1_b, w_qkv, w_out, w_p0, w_p2);
    // 2. qkv = y_ln @ w_qkv  (fp16 out)
    gemm_f16<<<dim3(3, TOTTOK / 64), 256>>>(yln_h, wqkv_h, nullptr, nullptr, qkv_h,
                                            TOTTOK, 384, 128, 2, nullptr);
    // 3. attention (64-key chunks)
    k_attn_mma<<<NREG * NHEADS, 256>>>();
    // 4. tok2 = o @ w_out + b_out + tok_raw
    gemm_f16<<<dim3(1, TOTTOK / 64), 256>>>(oattn_h, wout_h, b_out, tok_raw_h, tok2_h,
                                            TOTTOK, 128, 128, 3, nullptr);
    // 5. overlap merge + LN2 (2 pixels/block)
    k_merge_ln2<<<TOTPIX / 2, 256>>>(ln2_g, ln2_b);
    // 6. h0 = y2 @ w_p0 + b_p0
    gemm_f16<<<dim3(2, TOTPIX / 64), 256>>>(y2_h, wp0_h, b_p0, nullptr, h0_h,
                                            TOTPIX, 256, 128, 2, nullptr);
    // 7. row-blocked depthwise conv + BN partials
    k_dwconv<<<512, 256>>>(dw_k);
    // 8/9. batchnorm reduction
    k_bnmid<<<32, 256>>>();
    k_bnfinal<<<1, 256>>>(bn_g, bn_b);
    // 10. final GEMM (act fused, NCHW fp32 out)
    gemm_f16<<<dim3(1, TOTPIX / 64), 256>>>(conv_h, wp2_h, b_p2, xf_h, (float*)d_out,
                                            TOTPIX, 128, 256, 1, bnp);
}

// round 17
// speedup vs baseline: 1.0238x; 1.0238x over previous
#include <cuda_runtime.h>
#include <cuda_fp16.h>
#include <cstdint>
#include <math.h>

// ---------------- problem constants ----------------
#define BATCH   4
#define CDIM    128
#define HH      128
#define WW      128
#define RS      16
#define STEP    14
#define NR      9
#define NREG    (BATCH*NR*NR)      // 324
#define NTOK    (RS*RS)            // 256
#define TOTTOK  (NREG*NTOK)        // 82944
#define NHEADS  4
#define HD      32
#define HIDDEN  256
#define NPIX    (HH*WW)            // 16384
#define TOTPIX  (BATCH*NPIX)       // 65536

// ---------------- scratch ----------------
__device__ __half g_tok_raw_h[(size_t)TOTTOK*CDIM];
__device__ __half g_yln_h [(size_t)TOTTOK*CDIM];
__device__ __half g_qkv_h [(size_t)TOTTOK*3*CDIM];
__device__ __half g_oattn_h[(size_t)TOTTOK*CDIM];
__device__ __half g_tok2_h[(size_t)TOTTOK*CDIM];
__device__ __half g_xf_h  [(size_t)TOTPIX*CDIM];
__device__ __half g_y2_h  [(size_t)TOTPIX*CDIM];
__device__ __half g_h0_h  [(size_t)TOTPIX*HIDDEN];
__device__ __half g_conv_h[(size_t)TOTPIX*HIDDEN];
__device__ float  g_part  [2*512*HIDDEN];
__device__ float  g_mid   [2*32*HIDDEN];
__device__ float  g_bnp   [2*HIDDEN];
// fp16 transposed weights [N][K]
__device__ __half g_wqkv_h[384*128];
__device__ __half g_wout_h[128*128];
__device__ __half g_wp0_h [256*128];
__device__ __half g_wp2_h [128*256];

// ---------------- helpers ----------------
__device__ __forceinline__ float gelu_exact(float x) {
    return 0.5f * x * (1.0f + erff(x * 0.70710678118654752f));
}
__device__ __forceinline__ unsigned pack_h2(float a, float b) {
    __half2 h = __floats2half2_rn(a, b);
    return *(unsigned*)&h;
}
__device__ __forceinline__ float ex2(float x) {
    float y; asm("ex2.approx.ftz.f32 %0, %1;" : "=f"(y) : "f"(x)); return y;
}
__device__ __forceinline__ void mma_f16(float* c, const unsigned* a, const unsigned* b) {
    asm volatile(
        "mma.sync.aligned.m16n8k16.row.col.f32.f16.f16.f32 "
        "{%0,%1,%2,%3},{%4,%5,%6,%7},{%8,%9},{%0,%1,%2,%3};"
        : "+f"(c[0]), "+f"(c[1]), "+f"(c[2]), "+f"(c[3])
        : "r"(a[0]), "r"(a[1]), "r"(a[2]), "r"(a[3]), "r"(b[0]), "r"(b[1]));
}
__device__ __forceinline__ void ldsm4(unsigned& r0, unsigned& r1, unsigned& r2, unsigned& r3,
                                      unsigned addr) {
    asm volatile("ldmatrix.sync.aligned.m8n8.x4.shared.b16 {%0,%1,%2,%3}, [%4];"
                 : "=r"(r0), "=r"(r1), "=r"(r2), "=r"(r3) : "r"(addr));
}
__device__ __forceinline__ void ldsm4t(unsigned& r0, unsigned& r1, unsigned& r2, unsigned& r3,
                                       unsigned addr) {
    asm volatile("ldmatrix.sync.aligned.m8n8.x4.trans.shared.b16 {%0,%1,%2,%3}, [%4];"
                 : "=r"(r0), "=r"(r1), "=r"(r2), "=r"(r3) : "r"(addr));
}
__device__ __forceinline__ void cp16(void* smem_dst, const void* gsrc) {
    unsigned d = (unsigned)__cvta_generic_to_shared(smem_dst);
    asm volatile("cp.async.cg.shared.global [%0], [%1], 16;\n" :: "r"(d), "l"(gsrc));
}

// ---------------- kernel 1: merged weight-convert + region gather + LN1 ----------------
__device__ void wconv_body(int blk, int tid,
                           const float* wqkv, const float* wout,
                           const float* wp0, const float* wp2) {
    int idx = blk * 256 + tid;
    const float* in; __half* out; int K, local;
    int N;
    if (idx < 49152)       { in = wqkv; out = g_wqkv_h; K = 128; N = 384; local = idx; }
    else if (idx < 65536)  { in = wout; out = g_wout_h; K = 128; N = 128; local = idx - 49152; }
    else if (idx < 98304)  { in = wp0;  out = g_wp0_h;  K = 128; N = 256; local = idx - 65536; }
    else                   { in = wp2;  out = g_wp2_h;  K = 256; N = 128; local = idx - 98304; }
    int n = local / K, k = local % K;
    out[local] = __float2half(in[k * N + n]);
}

__global__ void k_front(const float* __restrict__ x,
                        const float* __restrict__ g,
                        const float* __restrict__ b,
                        const float* __restrict__ wqkv, const float* __restrict__ wout,
                        const float* __restrict__ wp0,  const float* __restrict__ wp2) {
    __shared__ float sTok[8][132];
    int tid = threadIdx.x;
    if (blockIdx.x < 512) { wconv_body(blockIdx.x, tid, wqkv, wout, wp0, wp2); return; }
    int blk = blockIdx.x - 512;
    int grp = blk & 1;
    int ti  = (blk >> 1) & 15;
    int region = blk >> 5;
    int breg = region / (NR * NR);
    int rem  = region % (NR * NR);
    int rr = rem / NR, rc = rem % NR;
    int hh = rr * STEP + ti;
    int ww0 = rc * STEP + grp * 8;
    int tj8 = tid & 7;
    int cbase = tid >> 3;
    #pragma unroll
    for (int chunk = 0; chunk < 4; chunk++) {
        int c = cbase + chunk * 32;
        sTok[tj8][c] = x[(((size_t)breg * CDIM + c) * HH + hh) * WW + ww0 + tj8];
    }
    __syncthreads();
    int w = tid >> 5, lane = tid & 31;
    float4 v = *(const float4*)&sTok[w][lane * 4];
    float sum = v.x + v.y + v.z + v.w;
    float sq  = v.x*v.x + v.y*v.y + v.z*v.z + v.w*v.w;
    #pragma unroll
    for (int o = 16; o > 0; o >>= 1) {
        sum += __shfl_xor_sync(0xffffffffu, sum, o);
        sq  += __shfl_xor_sync(0xffffffffu, sq,  o);
    }
    float mean = sum * (1.0f / 128.0f);
    float invstd = rsqrtf(sq * (1.0f / 128.0f) - mean * mean + 1e-5f);
    int tok = region * NTOK + ti * 16 + grp * 8 + w;
    float4 gg = *(const float4*)(g + lane * 4);
    float4 bb = *(const float4*)(b + lane * 4);
    size_t o = (size_t)tok * CDIM + lane * 4;
    __half2* tp = (__half2*)(g_tok_raw_h + o);
    tp[0] = __floats2half2_rn(v.x, v.y);
    tp[1] = __floats2half2_rn(v.z, v.w);
    float y0 = (v.x - mean) * invstd * gg.x + bb.x;
    float y1 = (v.y - mean) * invstd * gg.y + bb.y;
    float y2 = (v.z - mean) * invstd * gg.z + bb.z;
    float y3 = (v.w - mean) * invstd * gg.w + bb.w;
    __half2* yp = (__half2*)(g_yln_h + o);
    yp[0] = __floats2half2_rn(y0, y1);
    yp[1] = __floats2half2_rn(y2, y3);
}

// ---------------- 3-stage pipelined fp16 tensor-core GEMM, BK=32 ----------------
#define ASTRIDE 40
#define ABUF    (64*ASTRIDE)
#define BSTRIDE 40
#define BBUF    (128*BSTRIDE)
#define ST_STRIDE 72

__global__ void __launch_bounds__(256) gemm_f16(
        const __half* __restrict__ Ah, const __half* __restrict__ B,
        const float* __restrict__ bias, const __half* __restrict__ resh,
        void* __restrict__ Cp, int M, int N, int K, int mode,
        const float* __restrict__ actp) {
    __shared__ __align__(16) char smem_raw[46080];   // 3-stage pipeline 46080 B; staging 36864 B
    __half* As = (__half*)smem_raw;                  // [3][64][40]
    __half* Bs = (__half*)(smem_raw + 3 * ABUF * 2); // [3][128][40]
    int bm = blockIdx.y * 64, bn = blockIdx.x * 128;
    int tid = threadIdx.x, lane = tid & 31, wid = tid >> 5;
    int wm = wid & 1, wn = wid >> 1;
    int lr = lane >> 2, lc = lane & 3;

    float* Cf = (float*)Cp;
    __half* Ch = (__half*)Cp;

    float acc[2][4][4];
    #pragma unroll
    for (int i = 0; i < 2; i++)
        #pragma unroll
        for (int j = 0; j < 4; j++)
            #pragma unroll
            for (int t = 0; t < 4; t++) acc[i][j][t] = 0.f;

    float a8v[8];
    int arow = tid >> 2, ac = tid & 3;
    auto prefetchA = [&](int k0, int buf) {
        cp16(As + buf * ABUF + arow * ASTRIDE + ac * 8,
             Ah + (size_t)(bm + arow) * K + k0 + ac * 8);
    };
    auto prefetchB = [&](int k0, int buf) {
        #pragma unroll
        for (int i = 0; i < 2; i++) {
            int id = tid * 2 + i;
            int brow = id >> 2, bc = id & 3;
            cp16(Bs + buf * BBUF + brow * BSTRIDE + bc * 8,
                 B + (size_t)(bn + brow) * K + k0 + bc * 8);
        }
    };
    auto ldgA = [&](int k0) {
        uint4 u = *(const uint4*)(Ah + (size_t)(bm + arow) * K + k0 + ac * 8);
        float2 f0 = __half22float2(*(__half2*)&u.x);
        float2 f1 = __half22float2(*(__half2*)&u.y);
        float2 f2 = __half22float2(*(__half2*)&u.z);
        float2 f3 = __half22float2(*(__half2*)&u.w);
        a8v[0] = f0.x; a8v[1] = f0.y; a8v[2] = f1.x; a8v[3] = f1.y;
        a8v[4] = f2.x; a8v[5] = f2.y; a8v[6] = f3.x; a8v[7] = f3.y;
    };
    auto actStsA = [&](int k0, int buf) {
        int ch = k0 + ac * 8;
        __half2* dp = (__half2*)(As + buf * ABUF + arow * ASTRIDE + ac * 8);
        #pragma unroll
        for (int u = 0; u < 4; u++) {
            float v0 = gelu_exact(gelu_exact(a8v[2*u]   * actp[ch+2*u]   + actp[HIDDEN+ch+2*u]));
            float v1 = gelu_exact(gelu_exact(a8v[2*u+1] * actp[ch+2*u+1] + actp[HIDDEN+ch+2*u+1]));
            dp[u] = __floats2half2_rn(v0, v1);
        }
    };

    int rowoff = ((lane >> 3) & 1) * 8 + (lane & 7);
    int coloff = (lane >> 4) * 8;
    unsigned abase = (unsigned)__cvta_generic_to_shared(
        As + (wm * 32 + rowoff) * ASTRIDE + coloff);
    unsigned bbase = (unsigned)__cvta_generic_to_shared(
        Bs + (wn * 32 + rowoff) * BSTRIDE + coloff);
    const unsigned ABUFB = ABUF * 2, BBUFB = BBUF * 2;
    const unsigned AI16  = 16 * ASTRIDE * 2;
    const unsigned BN16  = 16 * BSTRIDE * 2;

    int T = K >> 5;
    // prologue: fill stages 0 and 1
    if (actp) { ldgA(0); actStsA(0, 0); prefetchB(0, 0); }
    else      { prefetchA(0, 0); prefetchB(0, 0); }
    asm volatile("cp.async.commit_group;\n");
    if (T > 1) {
        if (actp) { ldgA(32); actStsA(32, 1); prefetchB(32, 1); }
        else      { prefetchA(32, 1); prefetchB(32, 1); }
    }
    asm volatile("cp.async.commit_group;\n");

    for (int t = 0; t < T; t++) {
        int buf = t % 3;
        asm volatile("cp.async.wait_group 1;\n");
        __syncthreads();
        if (t + 2 < T) {
            int k2 = (t + 2) << 5;
            int nbuf = (t + 2) % 3;
            if (actp) { ldgA(k2); prefetchB(k2, nbuf); }
            else      { prefetchA(k2, nbuf); prefetchB(k2, nbuf); }
        }
        asm volatile("cp.async.commit_group;\n");
        #pragma unroll
        for (int ks = 0; ks < 2; ks++) {
            unsigned a[2][4], bf[4][2];
            ldsm4(a[0][0], a[0][1], a[0][2], a[0][3],
                  abase + buf * ABUFB + ks * 32);
            ldsm4(a[1][0], a[1][1], a[1][2], a[1][3],
                  abase + buf * ABUFB + AI16 + ks * 32);
            ldsm4(bf[0][0], bf[1][0], bf[0][1], bf[1][1],
                  bbase + buf * BBUFB + ks * 32);
            ldsm4(bf[2][0], bf[3][0], bf[2][1], bf[3][1],
                  bbase + buf * BBUFB + BN16 + ks * 32);
            #pragma unroll
            for (int i = 0; i < 2; i++)
                #pragma unroll
                for (int j = 0; j < 4; j++)
                    mma_f16(acc[i][j], a[i], bf[j]);
        }
        if (actp && t + 2 < T) actStsA((t + 2) << 5, (t + 2) % 3);
    }

    if (mode == 2 || mode == 3) {
        #pragma unroll
        for (int i = 0; i < 2; i++) {
            int r0 = bm + wm * 32 + i * 16 + lr;
            #pragma unroll
            for (int j = 0; j < 4; j++) {
                int c0 = bn + wn * 32 + j * 8 + lc * 2;
                float b0 = bias ? bias[c0] : 0.f, b1 = bias ? bias[c0 + 1] : 0.f;
                float v00 = acc[i][j][0] + b0, v01 = acc[i][j][1] + b1;
                float v10 = acc[i][j][2] + b0, v11 = acc[i][j][3] + b1;
                if (mode == 3) {
                    float2 r0f = __half22float2(*(const __half2*)(resh + (size_t)r0 * N + c0));
                    float2 r1f = __half22float2(*(const __half2*)(resh + (size_t)(r0 + 8) * N + c0));
                    v00 += r0f.x; v01 += r0f.y; v10 += r1f.x; v11 += r1f.y;
                }
                *(__half2*)(Ch + (size_t)r0 * N + c0) = __floats2half2_rn(v00, v01);
                *(__half2*)(Ch + (size_t)(r0 + 8) * N + c0) = __floats2half2_rn(v10, v11);
            }
        }
    } else {
        float* sT = (float*)smem_raw;    // [128][72]
        __syncthreads();
        #pragma unroll
        for (int i = 0; i < 2; i++)
            #pragma unroll
            for (int j = 0; j < 4; j++)
                #pragma unroll
                for (int t = 0; t < 4; t++) {
                    int m = wm * 32 + i * 16 + (t >> 1) * 8 + lr;
                    int nr = wn * 32 + j * 8 + lc * 2 + (t & 1);
                    int n = bn + nr;
                    float v = acc[i][j][t];
                    if (bias) v += bias[n];
                    if (resh) v += __half2float(resh[(size_t)(bm + m) * N + n]);
                    sT[nr * ST_STRIDE + m] = v;
                }
        __syncthreads();
        int bidx = bm >> 14, p0 = bm & 16383;
        int nrow = tid >> 1, seg = tid & 1;
        const float* srcrow = sT + nrow * ST_STRIDE;
        float* dst = Cf + ((size_t)(bidx * 128 + bn + nrow)) * 16384 + p0;
        #pragma unroll
        for (int u = 0; u < 8; u++) {
            int f = seg * 32 + u * 4;
            float4 v = *(const float4*)(srcrow + f);
            *(float4*)(dst + f) = v;
        }
    }
}

// ---------------- kernel 3: fp16 flash attention (R15 32-key version) ----------------
#define KVSTRIDE 40   // halves per row
__global__ void __launch_bounds__(256, 3) k_attn_mma() {
    __shared__ __half Ks[2][32][KVSTRIDE];
    __shared__ __half Vs[2][32][KVSTRIDE];
    int region = blockIdx.x >> 2;
    int head   = blockIdx.x & 3;
    const __half* base = g_qkv_h + (size_t)region * NTOK * 384;
    int hoff = head * HD;
    int tid = threadIdx.x, lane = tid & 31, w = tid >> 5;
    int lr = lane >> 2, lc = lane & 3;
    const float qscale = 0.17677669529663687f * 1.44269504088896341f;

    unsigned aq[2][2][4];
    #pragma unroll
    for (int kstep = 0; kstep < 2; kstep++)
        #pragma unroll
        for (int i = 0; i < 2; i++) {
            int r = w * 32 + i * 16 + lr;
            const __half* qp = base + (size_t)r * 384 + hoff + kstep * 16;
            unsigned u[4];
            u[0] = *(const unsigned*)(qp + 2 * lc);
            u[1] = *(const unsigned*)(qp + 8 * 384 + 2 * lc);
            u[2] = *(const unsigned*)(qp + 2 * lc + 8);
            u[3] = *(const unsigned*)(qp + 8 * 384 + 2 * lc + 8);
            #pragma unroll
            for (int t = 0; t < 4; t++) {
                float2 f = __half22float2(*(__half2*)&u[t]);
                aq[kstep][i][t] = pack_h2(f.x * qscale, f.y * qscale);
            }
        }

    float l[2][2], o[2][4][4];
    #pragma unroll
    for (int i = 0; i < 2; i++)
        #pragma unroll
        for (int h = 0; h < 2; h++) l[i][h] = 0.f;
    #pragma unroll
    for (int i = 0; i < 2; i++)
        #pragma unroll
        for (int jo = 0; jo < 4; jo++)
            #pragma unroll
            for (int t = 0; t < 4; t++) o[i][jo][t] = 0.f;

    int tile = lane >> 3, trow = lane & 7;
    unsigned kaddr = (unsigned)__cvta_generic_to_shared(
        &Ks[0][(tile >> 1) * 8 + trow][(tile & 1) * 8]);
    unsigned vaddr = (unsigned)__cvta_generic_to_shared(
        &Vs[0][(tile & 1) * 8 + trow][(tile >> 1) * 8]);
    const unsigned BUFOFF = 32 * KVSTRIDE * 2;
    const unsigned J2OFF  = 16 * KVSTRIDE * 2;
    const unsigned KS_K   = 32;
    const unsigned KS_V   = 16 * KVSTRIDE * 2;
    const unsigned JO2_V  = 32;

    int lm = tid >> 7, lrw = (tid >> 2) & 31, lch = tid & 3;
    auto loadKV = [&](int c0, int buf) {
        const __half* rp = base + (size_t)(c0 + lrw) * 384 + 128 + lm * 128 + hoff + lch * 8;
        cp16(lm ? &Vs[buf][lrw][lch * 8] : &Ks[buf][lrw][lch * 8], rp);
        asm volatile("cp.async.commit_group;\n");
    };

    loadKV(0, 0);
    for (int t = 0; t < 8; t++) {
        int buf = t & 1;
        asm volatile("cp.async.wait_group 0;\n");
        __syncthreads();
        if (t < 7) loadKV((t + 1) * 32, buf ^ 1);
        unsigned kb = kaddr + buf * BUFOFF;
        unsigned vb = vaddr + buf * BUFOFF;

        float s[2][4][4];
        #pragma unroll
        for (int i = 0; i < 2; i++)
            #pragma unroll
            for (int j = 0; j < 4; j++)
                #pragma unroll
                for (int tt = 0; tt < 4; tt++) s[i][j][tt] = 0.f;
        #pragma unroll
        for (int kstep = 0; kstep < 2; kstep++) {
            unsigned bf[4][2];
            ldsm4(bf[0][0], bf[0][1], bf[1][0], bf[1][1], kb + kstep * KS_K);
            ldsm4(bf[2][0], bf[2][1], bf[3][0], bf[3][1], kb + kstep * KS_K + J2OFF);
            #pragma unroll
            for (int i = 0; i < 2; i++)
                #pragma unroll
                for (int j = 0; j < 4; j++)
                    mma_f16(s[i][j], aq[kstep][i], bf[j]);
        }

        #pragma unroll
        for (int i = 0; i < 2; i++) {
            #pragma unroll
            for (int j = 0; j < 4; j++) {
                s[i][j][0] = ex2(s[i][j][0]);
                s[i][j][1] = ex2(s[i][j][1]);
                s[i][j][2] = ex2(s[i][j][2]);
                s[i][j][3] = ex2(s[i][j][3]);
                l[i][0] += s[i][j][0] + s[i][j][1];
                l[i][1] += s[i][j][2] + s[i][j][3];
            }
        }

        #pragma unroll
        for (int kstep = 0; kstep < 2; kstep++) {
            unsigned bv[4][2];
            ldsm4t(bv[0][0], bv[0][1], bv[1][0], bv[1][1], vb + kstep * KS_V);
            ldsm4t(bv[2][0], bv[2][1], bv[3][0], bv[3][1], vb + kstep * KS_V + JO2_V);
            #pragma unroll
            for (int i = 0; i < 2; i++) {
                unsigned ap[4];
                ap[0] = pack_h2(s[i][2 * kstep][0],     s[i][2 * kstep][1]);
                ap[1] = pack_h2(s[i][2 * kstep][2],     s[i][2 * kstep][3]);
                ap[2] = pack_h2(s[i][2 * kstep + 1][0], s[i][2 * kstep + 1][1]);
                ap[3] = pack_h2(s[i][2 * kstep + 1][2], s[i][2 * kstep + 1][3]);
                #pragma unroll
                for (int jo = 0; jo < 4; jo++)
                    mma_f16(o[i][jo], ap, bv[jo]);
            }
        }
    }

    #pragma unroll
    for (int i = 0; i < 2; i++)
        #pragma unroll
        for (int h = 0; h < 2; h++)
            #pragma unroll
            for (int off = 1; off <= 2; off <<= 1)
                l[i][h] += __shfl_xor_sync(0xffffffffu, l[i][h], off);

    #pragma unroll
    for (int i = 0; i < 2; i++) {
        float inv0 = 1.0f / l[i][0], inv1 = 1.0f / l[i][1];
        #pragma unroll
        for (int h = 0; h < 2; h++) {
            int q = w * 32 + i * 16 + lr + h * 8;
            float inv = h ? inv1 : inv0;
            __half* op = g_oattn_h + ((size_t)region * NTOK + q) * CDIM + hoff;
            #pragma unroll
            for (int jo = 0; jo < 4; jo++) {
                *(__half2*)(op + jo * 8 + lc * 2) =
                    __floats2half2_rn(o[i][jo][h * 2 + 0] * inv,
                                      o[i][jo][h * 2 + 1] * inv);
            }
        }
    }
}

// ---------------- kernel 5: overlap-merge + LN2 (R15 1-pixel version) ----------------
__global__ void k_merge_ln2(const float* __restrict__ g, const float* __restrict__ b) {
    int pix = blockIdx.x;
    int c = threadIdx.x;
    int bidx = pix >> 14;
    int p = pix & 16383;
    int hh = p >> 7, ww = p & 127;
    int rlo = max(0, (hh - 2) / STEP), rhi = min(NR - 1, hh / STEP);
    int clo = max(0, (ww - 2) / STEP), chi = min(NR - 1, ww / STEP);
    float sum = 0.f;
    int cnt = (rhi - rlo + 1) * (chi - clo + 1);
    for (int rr = rlo; rr <= rhi; rr++)
        for (int rc = clo; rc <= chi; rc++) {
            int region = bidx * (NR * NR) + rr * NR + rc;
            int t = (hh - rr * STEP) * RS + (ww - rc * STEP);
            sum += __half2float(g_tok2_h[((size_t)region * NTOK + t) * CDIM + c]);
        }
    float v = sum / (float)cnt;
    __shared__ float s1[4], s2[4];
    float su = v, sq = v * v;
    #pragma unroll
    for (int o = 16; o > 0; o >>= 1) {
        su += __shfl_xor_sync(0xffffffffu, su, o);
        sq += __shfl_xor_sync(0xffffffffu, sq, o);
    }
    int w = threadIdx.x >> 5;
    if ((threadIdx.x & 31) == 0) { s1[w] = su; s2[w] = sq; }
    __syncthreads();
    float ts = s1[0] + s1[1] + s1[2] + s1[3];
    float tq = s2[0] + s2[1] + s2[2] + s2[3];
    float mean = ts * (1.0f / 128.0f);
    float invstd = rsqrtf(tq * (1.0f / 128.0f) - mean * mean + 1e-5f);
    size_t o = (size_t)pix * CDIM + c;
    g_xf_h[o] = __float2half(v);
    g_y2_h[o] = __float2half((v - mean) * invstd * g[c] + b[c]);
}

// ---------------- kernel 7: row-blocked depthwise 5x5 conv (fp16) + BN partials ----------------
__global__ void k_dwconv(const float* __restrict__ k5) {
    int blk = blockIdx.x;                // 512
    int cg = blk & 3;
    int rg = (blk >> 2) & 31;
    int bidx = blk >> 7;
    int ch = threadIdx.x;
    int hh0 = rg * 4;
    int w0 = cg * 32;
    float kw[25];
    #pragma unroll
    for (int i = 0; i < 25; i++) kw[i] = k5[ch * 25 + i];
    const __half* base = g_h0_h + (size_t)bidx * NPIX * HIDDEN + ch;
    float win[5][8];
    auto loadcol = [&](int xx, float* col) {
        #pragma unroll
        for (int ry = 0; ry < 8; ry++) {
            int yy = hh0 - 2 + ry;
            col[ry] = ((unsigned)xx < (unsigned)WW && (unsigned)yy < (unsigned)HH)
                      ? __half2float(base[((size_t)(yy * WW + xx)) * HIDDEN]) : 0.f;
        }
    };
    #pragma unroll
    for (int xi = 0; xi < 4; xi++) loadcol(w0 - 2 + xi, win[xi]);
    float psum = 0.f, psq = 0.f;
    __half* outb = g_conv_h + ((size_t)bidx * NPIX + hh0 * WW) * HIDDEN + ch;
    for (int ww = w0; ww < w0 + 32; ww++) {
        loadcol(ww + 2, win[4]);
        #pragma unroll
        for (int r = 0; r < 4; r++) {
            float acc = 0.f;
            #pragma unroll
            for (int dy = 0; dy < 5; dy++)
                #pragma unroll
                for (int dx = 0; dx < 5; dx++)
                    acc += win[dx][r + dy] * kw[dy * 5 + dx];
            outb[((size_t)(r * WW + ww)) * HIDDEN] = __float2half(acc);
            psum += acc; psq += acc * acc;
        }
        #pragma unroll
        for (int xi = 0; xi < 4; xi++)
            #pragma unroll
            for (int ry = 0; ry < 8; ry++) win[xi][ry] = win[xi + 1][ry];
    }
    g_part[blk * HIDDEN + ch] = psum;
    g_part[512 * HIDDEN + blk * HIDDEN + ch] = psq;
}

// ---------------- batchnorm reduction ----------------
__global__ void k_bnmid() {
    int ch = threadIdx.x;
    int b = blockIdx.x;
    float s = 0.f, q = 0.f;
    for (int i = 0; i < 16; i++) {
        int idx = (b * 16 + i) * HIDDEN + ch;
        s += g_part[idx];
        q += g_part[512 * HIDDEN + idx];
    }
    g_mid[b * HIDDEN + ch] = s;
    g_mid[32 * HIDDEN + b * HIDDEN + ch] = q;
}
__global__ void k_bnfinal(const float* __restrict__ bg, const float* __restrict__ bb) {
    int ch = threadIdx.x;
    float s = 0.f, q = 0.f;
    for (int i = 0; i < 32; i++) {
        s += g_mid[i * HIDDEN + ch];
        q += g_mid[32 * HIDDEN + i * HIDDEN + ch];
    }
    float mean = s * (1.0f / (float)TOTPIX);
    float var  = q * (1.0f / (float)TOTPIX) - mean * mean;
    float sc = bg[ch] * rsqrtf(var + 1e-5f);
    g_bnp[ch] = sc;
    g_bnp[HIDDEN + ch] = bb[ch] - mean * sc;
}

// ---------------- host launcher ----------------
extern "C" void kernel_launch(void* const* d_in, const int* in_sizes, int n_in,
                              void* d_out, int out_size) {
    const float* x      = (const float*)d_in[0];
    const float* ln1_g  = (const float*)d_in[1];
    const float* ln1_b  = (const float*)d_in[2];
    const float* w_qkv  = (const float*)d_in[3];
    const float* w_out  = (const float*)d_in[4];
    const float* b_out  = (const float*)d_in[5];
    const float* ln2_g  = (const float*)d_in[6];
    const float* ln2_b  = (const float*)d_in[7];
    const float* w_p0   = (const float*)d_in[8];
    const float* b_p0   = (const float*)d_in[9];
    const float* dw_k   = (const float*)d_in[10];
    const float* bn_g   = (const float*)d_in[11];
    const float* bn_b   = (const float*)d_in[12];
    const float* w_p2   = (const float*)d_in[13];
    const float* b_p2   = (const float*)d_in[14];
    (void)in_sizes; (void)n_in; (void)out_size;

    float *bnp;
    __half *tok_raw_h, *yln_h, *qkv_h, *oattn_h, *tok2_h, *xf_h, *y2_h, *h0_h, *conv_h;
    __half *wqkv_h, *wout_h, *wp0_h, *wp2_h;
    cudaGetSymbolAddress((void**)&tok_raw_h, g_tok_raw_h);
    cudaGetSymbolAddress((void**)&yln_h,   g_yln_h);
    cudaGetSymbolAddress((void**)&qkv_h,   g_qkv_h);
    cudaGetSymbolAddress((void**)&oattn_h, g_oattn_h);
    cudaGetSymbolAddress((void**)&tok2_h,  g_tok2_h);
    cudaGetSymbolAddress((void**)&xf_h,    g_xf_h);
    cudaGetSymbolAddress((void**)&y2_h,    g_y2_h);
    cudaGetSymbolAddress((void**)&h0_h,    g_h0_h);
    cudaGetSymbolAddress((void**)&conv_h,  g_conv_h);
    cudaGetSymbolAddress((void**)&bnp,     g_bnp);
    cudaGetSymbolAddress((void**)&wqkv_h,  g_wqkv_h);
    cudaGetSymbolAddress((void**)&wout_h,  g_wout_h);
    cudaGetSymbolAddress((void**)&wp0_h,   g_wp0_h);
    cudaGetSymbolAddress((void**)&wp2_h,   g_wp2_h);

    // 1. merged: weight convert + region gather + LN1
    k_front<<<512 + TOTTOK / 8, 256>>>(x, ln1_g, ln1_b, w_qkv, w_out, w_p0, w_p2);
    // 2. qkv = y_ln @ w_qkv  (fp16 out)
    gemm_f16<<<dim3(3, TOTTOK / 64), 256>>>(yln_h, wqkv_h, nullptr, nullptr, qkv_h,
                                            TOTTOK, 384, 128, 2, nullptr);
    // 3. attention (32-key chunks)
    k_attn_mma<<<NREG * NHEADS, 256>>>();
    // 4. tok2 = o @ w_out + b_out + tok_raw
    gemm_f16<<<dim3(1, TOTTOK / 64), 256>>>(oattn_h, wout_h, b_out, tok_raw_h, tok2_h,
                                            TOTTOK, 128, 128, 3, nullptr);
    // 5. overlap merge + LN2
    k_merge_ln2<<<TOTPIX, 128>>>(ln2_g, ln2_b);
    // 6. h0 = y2 @ w_p0 + b_p0
    gemm_f16<<<dim3(2, TOTPIX / 64), 256>>>(y2_h, wp0_h, b_p0, nullptr, h0_h,
                                            TOTPIX, 256, 128, 2, nullptr);
    // 7. row-blocked depthwise conv + BN partials
    k_dwconv<<<512, 256>>>(dw_k);
    // 8/9. batchnorm reduction
    k_bnmid<<<32, 256>>>();
    k_bnfinal<<<1, 256>>>(bn_g, bn_b);
    // 10. final GEMM (act fused, NCHW fp32 out)
    gemm_f16<<<dim3(1, TOTPIX / 64), 256>>>(conv_h, wp2_h, b_p2, xf_h, (float*)d_out,
                                            TOTPIX, 128, 256, 1, bnp);
}